// round 15
// baseline (speedup 1.0000x reference)
#include <cuda_runtime.h>
#include <math.h>
#include <stdint.h>

#define D_MODEL 1024
#define N_HEADS 16
#define K_WIN   8
#define BATCH   2
#define SEQ     2048
#define M_TOTAL (BATCH * SEQ)          // 4096 tokens
#define QKV_COLS (3 * D_MODEL)         // 3072
#define K2      (2 * D_MODEL)          // 2048 tf32 cols (hi/lo interleaved)

// ---------------------------------------------------------------------------
// Scratch (__device__ globals, uint4-backed for 16B alignment).
// g_as (attention split output) aliases g_xs: x-split is dead after GEMM1.
// ---------------------------------------------------------------------------
__device__ uint4 g_qkv4[((size_t)M_TOTAL * QKV_COLS * 4) / 16];   // fp32 qkv (50 MB)
__device__ uint4 g_xs4 [((size_t)M_TOTAL * K2 * 4) / 16];         // tf32 split x / attn (33 MB)
__device__ uint4 g_wq4 [((size_t)QKV_COLS * K2 * 4) / 16];        // tf32 split qkv_w (25 MB)
__device__ uint4 g_wo4 [((size_t)D_MODEL * K2 * 4) / 16];         // tf32 split out_w (8 MB)

#define G_QKV ((float*)g_qkv4)
#define G_XS  ((uint32_t*)g_xs4)
#define G_WQ  ((uint32_t*)g_wq4)
#define G_WO  ((uint32_t*)g_wo4)
#define G_AS  ((uint32_t*)g_xs4)

// ---------------------------------------------------------------------------
// tf32 split helpers + cp.async
// ---------------------------------------------------------------------------
__device__ __forceinline__ uint32_t f2tf(float x) {
    uint32_t r;
    asm("cvt.rna.tf32.f32 %0, %1;" : "=r"(r) : "f"(x));
    return r;
}
__device__ __forceinline__ void tfpair(float x, uint32_t& hi, uint32_t& lo) {
    hi = f2tf(x);
    lo = f2tf(x - __uint_as_float(hi));
}
__device__ __forceinline__ uint32_t smem_u32(const void* p) {
    uint32_t a;
    asm("{ .reg .u64 t; cvta.to.shared.u64 t, %1; cvt.u32.u64 %0, t; }"
        : "=r"(a) : "l"(p));
    return a;
}
__device__ __forceinline__ void cp_async16(uint32_t dst, const void* src) {
    asm volatile("cp.async.cg.shared.global [%0], [%1], 16;" :: "r"(dst), "l"(src));
}
#define CP_COMMIT() asm volatile("cp.async.commit_group;" ::: "memory")
#define CP_WAIT(n)  asm volatile("cp.async.wait_group %0;" :: "n"(n) : "memory")

// mode: 0 -> G_XS, 1 -> G_WQ, 2 -> G_WO
__global__ __launch_bounds__(256)
void split_kernel(const float* __restrict__ src, int mode, int n4)
{
    int i = blockIdx.x * blockDim.x + threadIdx.x;
    if (i >= n4) return;
    uint32_t* dst = (mode == 0) ? G_XS : (mode == 1) ? G_WQ : G_WO;
    float4 v = __ldg((const float4*)src + i);
    uint4 h0, h1;
    tfpair(v.x, h0.x, h0.y);
    tfpair(v.y, h0.z, h0.w);
    tfpair(v.z, h1.x, h1.y);
    tfpair(v.w, h1.z, h1.w);
    *((uint4*)dst + 2 * i)     = h0;
    *((uint4*)dst + 2 * i + 1) = h1;
}

// ---------------------------------------------------------------------------
// tf32 mma.sync GEMM on pre-split operands, cp.async double-buffered:
// C[M,N] = A[M,K2]tf32 @ B[N,K2]tf32^T + bias (fp32 out)
// CTA tile 128x128, K-chunk 16, 256 threads / 8 warps (64x32 warp tile,
// 64 fp32 accs — the register class proven clean at <=128 regs).
// smem: 2 buffers x 2 operands x 128x20 u32 = 40 KB static.
// ---------------------------------------------------------------------------
#define BM   128
#define BN   128
#define BKT  16
#define PADT 20              // 16 u32 + 4 pad; banks (20g+t)%32 all distinct

__device__ __forceinline__
void tf32_gemm_body(const uint32_t* __restrict__ A,
                    const uint32_t* __restrict__ B,
                    const float* __restrict__ bias,
                    float* __restrict__ C,
                    int N)
{
    __shared__ uint32_t As[2][BM][PADT];
    __shared__ uint32_t Bs[2][BN][PADT];

    const int tid    = threadIdx.x;
    const int wid    = tid >> 5;
    const int lane   = tid & 31;
    const int g      = lane >> 2;      // group 0..7
    const int t      = lane & 3;       // thread-in-group
    const int warp_m = wid & 1;        // 0..1 (64-row slabs)
    const int warp_n = wid >> 1;       // 0..3 (32-col slabs)

    const int bm = blockIdx.y * BM;
    const int bn = blockIdx.x * BN;
    const uint32_t* Arow = A + (size_t)bm * K2;
    const uint32_t* Brow = B + (size_t)bn * K2;

    // Loader: 512 uint4-chunks per operand (128 rows x 4 uint4-cols);
    // thread covers chunks tid and tid+256 for BOTH operands.
    const int r0 = tid >> 2,         c40 = (tid & 3) * 4;
    const int r1 = (tid + 256) >> 2, c41 = ((tid + 256) & 3) * 4;

    float acc[4][4][4];
#pragma unroll
    for (int i = 0; i < 4; i++)
#pragma unroll
        for (int j = 0; j < 4; j++)
#pragma unroll
            for (int e = 0; e < 4; e++) acc[i][j][e] = 0.f;

    const int NITER = K2 / BKT;     // 128

    // Prologue: chunk 0 into buffer 0
    cp_async16(smem_u32(&As[0][r0][c40]), Arow + (size_t)r0 * K2 + c40);
    cp_async16(smem_u32(&As[0][r1][c41]), Arow + (size_t)r1 * K2 + c41);
    cp_async16(smem_u32(&Bs[0][r0][c40]), Brow + (size_t)r0 * K2 + c40);
    cp_async16(smem_u32(&Bs[0][r1][c41]), Brow + (size_t)r1 * K2 + c41);
    CP_COMMIT();

    for (int c = 0; c < NITER; c++) {
        const int buf = c & 1;
        if (c + 1 < NITER) {
            const int nb = buf ^ 1;
            const size_t k0 = (size_t)(c + 1) * BKT;
            cp_async16(smem_u32(&As[nb][r0][c40]), Arow + (size_t)r0 * K2 + k0 + c40);
            cp_async16(smem_u32(&As[nb][r1][c41]), Arow + (size_t)r1 * K2 + k0 + c41);
            cp_async16(smem_u32(&Bs[nb][r0][c40]), Brow + (size_t)r0 * K2 + k0 + c40);
            cp_async16(smem_u32(&Bs[nb][r1][c41]), Brow + (size_t)r1 * K2 + k0 + c41);
            CP_COMMIT();
            CP_WAIT(1);          // chunk c complete; c+1 still in flight
        } else {
            CP_WAIT(0);
        }
        __syncthreads();

#pragma unroll
        for (int s = 0; s < 2; s++) {
            const int kb = s * 8;
            const uint32_t b00 = Bs[buf][warp_n * 32 + 0 * 8 + g][kb + t];
            const uint32_t b01 = Bs[buf][warp_n * 32 + 0 * 8 + g][kb + t + 4];
            const uint32_t b10 = Bs[buf][warp_n * 32 + 1 * 8 + g][kb + t];
            const uint32_t b11 = Bs[buf][warp_n * 32 + 1 * 8 + g][kb + t + 4];
            const uint32_t b20 = Bs[buf][warp_n * 32 + 2 * 8 + g][kb + t];
            const uint32_t b21 = Bs[buf][warp_n * 32 + 2 * 8 + g][kb + t + 4];
            const uint32_t b30 = Bs[buf][warp_n * 32 + 3 * 8 + g][kb + t];
            const uint32_t b31 = Bs[buf][warp_n * 32 + 3 * 8 + g][kb + t + 4];
#pragma unroll
            for (int mf = 0; mf < 4; mf++) {
                const int mr = warp_m * 64 + mf * 16;
                const uint32_t a0 = As[buf][mr + g    ][kb + t];
                const uint32_t a1 = As[buf][mr + g + 8][kb + t];
                const uint32_t a2 = As[buf][mr + g    ][kb + t + 4];
                const uint32_t a3 = As[buf][mr + g + 8][kb + t + 4];
#define TF32_MMA(nf, bb0, bb1)                                          \
                asm volatile(                                           \
                    "mma.sync.aligned.m16n8k8.row.col.f32.tf32.tf32.f32 " \
                    "{%0,%1,%2,%3}, {%4,%5,%6,%7}, {%8,%9}, {%0,%1,%2,%3};" \
                    : "+f"(acc[mf][nf][0]), "+f"(acc[mf][nf][1]),       \
                      "+f"(acc[mf][nf][2]), "+f"(acc[mf][nf][3])        \
                    : "r"(a0), "r"(a1), "r"(a2), "r"(a3), "r"(bb0), "r"(bb1))
                TF32_MMA(0, b00, b01);
                TF32_MMA(1, b10, b11);
                TF32_MMA(2, b20, b21);
                TF32_MMA(3, b30, b31);
#undef TF32_MMA
            }
        }
        __syncthreads();
    }

    // Epilogue: acc e0,e1 -> (row g, cols 2t,2t+1); e2,e3 -> (row g+8).
#pragma unroll
    for (int mf = 0; mf < 4; mf++) {
        const int gr = bm + warp_m * 64 + mf * 16 + g;
#pragma unroll
        for (int nf = 0; nf < 4; nf++) {
            const int gc = bn + warp_n * 32 + nf * 8 + t * 2;
            const float b0 = __ldg(bias + gc);
            const float b1 = __ldg(bias + gc + 1);
            float2 v0 = make_float2(acc[mf][nf][0] + b0, acc[mf][nf][1] + b1);
            float2 v1 = make_float2(acc[mf][nf][2] + b0, acc[mf][nf][3] + b1);
            *(float2*)(C + (size_t)gr * N + gc)       = v0;
            *(float2*)(C + (size_t)(gr + 8) * N + gc) = v1;
        }
    }
}

__global__ __launch_bounds__(256)
void tf32_x_to_qkv(const float* __restrict__ qkv_b)
{
    tf32_gemm_body(G_XS, G_WQ, qkv_b, G_QKV, QKV_COLS);
}

__global__ __launch_bounds__(256)
void tf32_att_to_out(const float* __restrict__ out_b, float* __restrict__ out)
{
    tf32_gemm_body(G_AS, G_WO, out_b, out, D_MODEL);
}

// ---------------------------------------------------------------------------
// QK-norm: L2-normalize each 64-element head vector of q and k (in place).
// ---------------------------------------------------------------------------
__global__ __launch_bounds__(256)
void qknorm_kernel()
{
    int gw   = (blockIdx.x * blockDim.x + threadIdx.x) >> 5;
    int lane = threadIdx.x & 31;
    if (gw >= M_TOTAL * 32) return;
    int row = gw >> 5;
    int seg = gw & 31;
    size_t off = (size_t)row * QKV_COLS +
                 (seg < 16 ? seg * 64 : D_MODEL + (seg - 16) * 64);
    float* p = G_QKV + off;
    float2 v = *(float2*)(p + lane * 2);
    float ss = v.x * v.x + v.y * v.y;
#pragma unroll
    for (int o = 16; o; o >>= 1) ss += __shfl_xor_sync(0xFFFFFFFFu, ss, o);
    float inv = 1.0f / (sqrtf(ss) + 1e-6f);
    v.x *= inv; v.y *= inv;
    *(float2*)(p + lane * 2) = v;
}

// ---------------------------------------------------------------------------
// Dilated attention: one warp per (token, head). Output written pre-split
// (tf32 hi/lo interleaved) into G_AS for the second GEMM.
// ---------------------------------------------------------------------------
__global__ __launch_bounds__(256)
void attend_kernel()
{
    int gw   = (blockIdx.x * blockDim.x + threadIdx.x) >> 5;
    int lane = threadIdx.x & 31;
    if (gw >= M_TOTAL * N_HEADS) return;
    int r = gw >> 4;
    int h = gw & 15;
    int b = r / SEQ;
    int i = r % SEQ;

    const float* qp = G_QKV + (size_t)r * QKV_COLS + h * 64;
    const float* kb = G_QKV + (size_t)(b * SEQ) * QKV_COLS + D_MODEL + h * 64;
    const float* vb = G_QKV + (size_t)(b * SEQ) * QKV_COLS + 2 * D_MODEL + h * 64;

    float2 q = *(const float2*)(qp + lane * 2);

    float sc[17];
#pragma unroll
    for (int t = 0; t < 17; t++) {
        int j = i + 2 * (t - K_WIN);
        float s = -INFINITY;
        if (j >= 0 && j < SEQ) {
            float2 k = *(const float2*)(kb + (size_t)j * QKV_COLS + lane * 2);
            float d = q.x * k.x + q.y * k.y;
#pragma unroll
            for (int o = 16; o; o >>= 1) d += __shfl_xor_sync(0xFFFFFFFFu, d, o);
            s = d;
        }
        sc[t] = s;
    }

    float mx = -INFINITY;
#pragma unroll
    for (int t = 0; t < 17; t++) mx = fmaxf(mx, sc[t]);
    float den = 0.f;
#pragma unroll
    for (int t = 0; t < 17; t++) {
        float e = (sc[t] == -INFINITY) ? 0.f : __expf(sc[t] - mx);
        sc[t] = e;
        den += e;
    }
    float inv = 1.0f / den;   // den >= 1: diagonal always in window

    float2 acc = make_float2(0.f, 0.f);
#pragma unroll
    for (int t = 0; t < 17; t++) {
        int j = i + 2 * (t - K_WIN);
        if (j >= 0 && j < SEQ) {
            float2 v = *(const float2*)(vb + (size_t)j * QKV_COLS + lane * 2);
            float p = sc[t] * inv;
            acc.x = fmaf(p, v.x, acc.x);
            acc.y = fmaf(p, v.y, acc.y);
        }
    }

    // tf32 hi/lo split, interleaved: elem col e -> split cols 2e, 2e+1.
    uint4 w;
    tfpair(acc.x, w.x, w.y);
    tfpair(acc.y, w.z, w.w);
    *(uint4*)(G_AS + (size_t)r * K2 + 2 * (h * 64 + lane * 2)) = w;
}

// ---------------------------------------------------------------------------
// Launch (pure kernel launches; graph-capture safe)
// ---------------------------------------------------------------------------
extern "C" void kernel_launch(void* const* d_in, const int* in_sizes, int n_in,
                              void* d_out, int out_size)
{
    const float* x     = (const float*)d_in[0];
    const float* qkv_w = (const float*)d_in[1];
    const float* qkv_b = (const float*)d_in[2];
    const float* out_w = (const float*)d_in[3];
    const float* out_b = (const float*)d_in[4];
    float* out = (float*)d_out;

    // 0) Split prepasses (fp32 -> interleaved tf32 hi/lo)
    {
        int n4 = (M_TOTAL * D_MODEL) / 4;
        split_kernel<<<n4 / 256, 256>>>(x, 0, n4);
    }
    {
        int n4 = (QKV_COLS * D_MODEL) / 4;
        split_kernel<<<n4 / 256, 256>>>(qkv_w, 1, n4);
    }
    {
        int n4 = (D_MODEL * D_MODEL) / 4;
        split_kernel<<<n4 / 256, 256>>>(out_w, 2, n4);
    }

    // 1) QKV projection: G_XS @ G_WQ^T + qkv_b -> G_QKV fp32 (4096x3072)
    {
        dim3 grid(QKV_COLS / BN, M_TOTAL / BM);
        tf32_x_to_qkv<<<grid, 256>>>(qkv_b);
    }

    // 2) QK L2-normalization (in place on G_QKV)
    qknorm_kernel<<<(M_TOTAL * 32) / 8, 256>>>();

    // 3) Dilated windowed attention -> G_AS (tf32 hi/lo; aliases G_XS)
    attend_kernel<<<(M_TOTAL * N_HEADS) / 8, 256>>>();

    // 4) Output projection: G_AS @ G_WO^T + out_b -> out fp32 (4096x1024)
    {
        dim3 grid(D_MODEL / BN, M_TOTAL / BM);
        tf32_att_to_out<<<grid, 256>>>(out_b, out);
    }
}

// round 16
// speedup vs baseline: 1.1421x; 1.1421x over previous
#include <cuda_runtime.h>
#include <math.h>
#include <stdint.h>

#define D_MODEL 1024
#define N_HEADS 16
#define K_WIN   8
#define BATCH   2
#define SEQ     2048
#define M_TOTAL (BATCH * SEQ)          // 4096 tokens
#define QKV_COLS (3 * D_MODEL)         // 3072
#define K2      (2 * D_MODEL)          // 2048 tf32 cols (hi/lo interleaved)

// ---------------------------------------------------------------------------
// Scratch (__device__ globals, uint4-backed for 16B alignment).
// g_as (attention split output) aliases g_xs: x-split is dead after GEMM1.
// ---------------------------------------------------------------------------
__device__ uint4 g_qkv4[((size_t)M_TOTAL * QKV_COLS * 4) / 16];   // fp32 qkv (50 MB)
__device__ uint4 g_xs4 [((size_t)M_TOTAL * K2 * 4) / 16];         // tf32 split x / attn (33 MB)
__device__ uint4 g_wq4 [((size_t)QKV_COLS * K2 * 4) / 16];        // tf32 split qkv_w (25 MB)
__device__ uint4 g_wo4 [((size_t)D_MODEL * K2 * 4) / 16];         // tf32 split out_w (8 MB)

#define G_QKV ((float*)g_qkv4)
#define G_XS  ((uint32_t*)g_xs4)
#define G_WQ  ((uint32_t*)g_wq4)
#define G_WO  ((uint32_t*)g_wo4)
#define G_AS  ((uint32_t*)g_xs4)

// ---------------------------------------------------------------------------
// tf32 split helpers + cp.async
// ---------------------------------------------------------------------------
__device__ __forceinline__ uint32_t f2tf(float x) {
    uint32_t r;
    asm("cvt.rna.tf32.f32 %0, %1;" : "=r"(r) : "f"(x));
    return r;
}
__device__ __forceinline__ void tfpair(float x, uint32_t& hi, uint32_t& lo) {
    hi = f2tf(x);
    lo = f2tf(x - __uint_as_float(hi));
}
__device__ __forceinline__ uint32_t smem_u32(const void* p) {
    uint32_t a;
    asm("{ .reg .u64 t; cvta.to.shared.u64 t, %1; cvt.u32.u64 %0, t; }"
        : "=r"(a) : "l"(p));
    return a;
}
__device__ __forceinline__ void cp_async16(uint32_t dst, const void* src) {
    asm volatile("cp.async.cg.shared.global [%0], [%1], 16;" :: "r"(dst), "l"(src));
}
#define CP_COMMIT() asm volatile("cp.async.commit_group;" ::: "memory")
#define CP_WAIT0()  asm volatile("cp.async.wait_group 0;" ::: "memory")

// mode: 0 -> G_XS, 1 -> G_WQ, 2 -> G_WO
__global__ __launch_bounds__(256)
void split_kernel(const float* __restrict__ src, int mode, int n4)
{
    int i = blockIdx.x * blockDim.x + threadIdx.x;
    if (i >= n4) return;
    uint32_t* dst = (mode == 0) ? G_XS : (mode == 1) ? G_WQ : G_WO;
    float4 v = __ldg((const float4*)src + i);
    uint4 h0, h1;
    tfpair(v.x, h0.x, h0.y);
    tfpair(v.y, h0.z, h0.w);
    tfpair(v.z, h1.x, h1.y);
    tfpair(v.w, h1.z, h1.w);
    *((uint4*)dst + 2 * i)     = h0;
    *((uint4*)dst + 2 * i + 1) = h1;
}

// ---------------------------------------------------------------------------
// tf32 mma.sync GEMM on pre-split operands, cp.async double-buffered with
// ONE __syncthreads per K-chunk:
//   wait(chunk c) -> sync -> issue chunk c+1 into other buffer -> compute c
// The sync both publishes chunk c and proves all warps finished computing
// chunk c-1 (which lived in the buffer the new loads overwrite).
// CTA tile 128x128, BKT=32, 64 iterations, 256 threads / 8 warps (64x32
// warp tile, 64 fp32 accs). Dynamic smem: 2 bufs x 2 ops x 128x36 u32 = 72KB.
// ---------------------------------------------------------------------------
#define BM   128
#define BN   128
#define BKT  32
#define PADT 36              // 32 u32 + 4 pad; frag banks (4g+t) all distinct
#define GEMM_SMEM (2 * 2 * BM * PADT * 4)   // 73728 bytes

__device__ __forceinline__
void tf32_gemm_body(const uint32_t* __restrict__ A,
                    const uint32_t* __restrict__ B,
                    const float* __restrict__ bias,
                    float* __restrict__ C,
                    int N)
{
    extern __shared__ uint32_t smem_dyn[];
    // Layout: A buffers [2][BM][PADT], then B buffers [2][BN][PADT]
    uint32_t* const Abase = smem_dyn;
    uint32_t* const Bbase = smem_dyn + 2 * BM * PADT;

    const int tid    = threadIdx.x;
    const int wid    = tid >> 5;
    const int lane   = tid & 31;
    const int g      = lane >> 2;      // group 0..7
    const int t      = lane & 3;       // thread-in-group
    const int warp_m = wid & 1;        // 0..1 (64-row slabs)
    const int warp_n = wid >> 1;       // 0..3 (32-col slabs)

    const int bm = blockIdx.y * BM;
    const int bn = blockIdx.x * BN;
    const uint32_t* Arow = A + (size_t)bm * K2;
    const uint32_t* Brow = B + (size_t)bn * K2;

    // Loader: 1024 uint4 chunks per operand per K-chunk (128 rows x 8 u4-cols);
    // thread covers chunks tid, +256, +512, +768 for BOTH operands.
    const int r0 = tid >> 3,         c40 = (tid & 7) * 4;
    const int r1 = (tid + 256) >> 3, c41 = ((tid + 256) & 7) * 4;
    const int r2 = (tid + 512) >> 3, c42 = ((tid + 512) & 7) * 4;
    const int r3 = (tid + 768) >> 3, c43 = ((tid + 768) & 7) * 4;

    float acc[4][4][4];
#pragma unroll
    for (int i = 0; i < 4; i++)
#pragma unroll
        for (int j = 0; j < 4; j++)
#pragma unroll
            for (int e = 0; e < 4; e++) acc[i][j][e] = 0.f;

    const int NITER = K2 / BKT;     // 64

#define ISSUE_CHUNK(k0, buf) do {                                             \
    uint32_t* Ab = Abase + (buf) * (BM * PADT);                               \
    uint32_t* Bb = Bbase + (buf) * (BN * PADT);                               \
    cp_async16(smem_u32(Ab + r0 * PADT + c40), Arow + (size_t)r0 * K2 + (k0) + c40); \
    cp_async16(smem_u32(Ab + r1 * PADT + c41), Arow + (size_t)r1 * K2 + (k0) + c41); \
    cp_async16(smem_u32(Ab + r2 * PADT + c42), Arow + (size_t)r2 * K2 + (k0) + c42); \
    cp_async16(smem_u32(Ab + r3 * PADT + c43), Arow + (size_t)r3 * K2 + (k0) + c43); \
    cp_async16(smem_u32(Bb + r0 * PADT + c40), Brow + (size_t)r0 * K2 + (k0) + c40); \
    cp_async16(smem_u32(Bb + r1 * PADT + c41), Brow + (size_t)r1 * K2 + (k0) + c41); \
    cp_async16(smem_u32(Bb + r2 * PADT + c42), Brow + (size_t)r2 * K2 + (k0) + c42); \
    cp_async16(smem_u32(Bb + r3 * PADT + c43), Brow + (size_t)r3 * K2 + (k0) + c43); \
    CP_COMMIT();                                                              \
} while (0)

    // Prologue: chunk 0 into buffer 0
    ISSUE_CHUNK(0, 0);

    for (int c = 0; c < NITER; c++) {
        const int buf = c & 1;
        CP_WAIT0();              // chunk c resident (only group in flight)
        __syncthreads();         // publish chunk c; all warps done with buf^1

        if (c + 1 < NITER)
            ISSUE_CHUNK((c + 1) * BKT, buf ^ 1);   // overlaps compute below

        const uint32_t* Ab = Abase + buf * (BM * PADT);
        const uint32_t* Bb = Bbase + buf * (BN * PADT);

#pragma unroll
        for (int s = 0; s < 4; s++) {
            const int kb = s * 8;
            const uint32_t* Bw = Bb + (warp_n * 32 + g) * PADT + kb + t;
            const uint32_t b00 = Bw[0 * 8 * PADT];
            const uint32_t b01 = Bw[0 * 8 * PADT + 4];
            const uint32_t b10 = Bw[1 * 8 * PADT];
            const uint32_t b11 = Bw[1 * 8 * PADT + 4];
            const uint32_t b20 = Bw[2 * 8 * PADT];
            const uint32_t b21 = Bw[2 * 8 * PADT + 4];
            const uint32_t b30 = Bw[3 * 8 * PADT];
            const uint32_t b31 = Bw[3 * 8 * PADT + 4];
#pragma unroll
            for (int mf = 0; mf < 4; mf++) {
                const uint32_t* Aw = Ab + (warp_m * 64 + mf * 16 + g) * PADT + kb + t;
                const uint32_t a0 = Aw[0];
                const uint32_t a1 = Aw[8 * PADT];
                const uint32_t a2 = Aw[4];
                const uint32_t a3 = Aw[8 * PADT + 4];
#define TF32_MMA(nf, bb0, bb1)                                          \
                asm volatile(                                           \
                    "mma.sync.aligned.m16n8k8.row.col.f32.tf32.tf32.f32 " \
                    "{%0,%1,%2,%3}, {%4,%5,%6,%7}, {%8,%9}, {%0,%1,%2,%3};" \
                    : "+f"(acc[mf][nf][0]), "+f"(acc[mf][nf][1]),       \
                      "+f"(acc[mf][nf][2]), "+f"(acc[mf][nf][3])        \
                    : "r"(a0), "r"(a1), "r"(a2), "r"(a3), "r"(bb0), "r"(bb1))
                TF32_MMA(0, b00, b01);
                TF32_MMA(1, b10, b11);
                TF32_MMA(2, b20, b21);
                TF32_MMA(3, b30, b31);
#undef TF32_MMA
            }
        }
        // no trailing sync: next iteration's barrier provides the ordering
    }
#undef ISSUE_CHUNK

    // Epilogue: acc e0,e1 -> (row g, cols 2t,2t+1); e2,e3 -> (row g+8).
#pragma unroll
    for (int mf = 0; mf < 4; mf++) {
        const int gr = bm + warp_m * 64 + mf * 16 + g;
#pragma unroll
        for (int nf = 0; nf < 4; nf++) {
            const int gc = bn + warp_n * 32 + nf * 8 + t * 2;
            const float b0 = __ldg(bias + gc);
            const float b1 = __ldg(bias + gc + 1);
            float2 v0 = make_float2(acc[mf][nf][0] + b0, acc[mf][nf][1] + b1);
            float2 v1 = make_float2(acc[mf][nf][2] + b0, acc[mf][nf][3] + b1);
            *(float2*)(C + (size_t)gr * N + gc)       = v0;
            *(float2*)(C + (size_t)(gr + 8) * N + gc) = v1;
        }
    }
}

__global__ __launch_bounds__(256)
void tf32_x_to_qkv(const float* __restrict__ qkv_b)
{
    tf32_gemm_body(G_XS, G_WQ, qkv_b, G_QKV, QKV_COLS);
}

__global__ __launch_bounds__(256)
void tf32_att_to_out(const float* __restrict__ out_b, float* __restrict__ out)
{
    tf32_gemm_body(G_AS, G_WO, out_b, out, D_MODEL);
}

// ---------------------------------------------------------------------------
// QK-norm: L2-normalize each 64-element head vector of q and k (in place).
// ---------------------------------------------------------------------------
__global__ __launch_bounds__(256)
void qknorm_kernel()
{
    int gw   = (blockIdx.x * blockDim.x + threadIdx.x) >> 5;
    int lane = threadIdx.x & 31;
    if (gw >= M_TOTAL * 32) return;
    int row = gw >> 5;
    int seg = gw & 31;
    size_t off = (size_t)row * QKV_COLS +
                 (seg < 16 ? seg * 64 : D_MODEL + (seg - 16) * 64);
    float* p = G_QKV + off;
    float2 v = *(float2*)(p + lane * 2);
    float ss = v.x * v.x + v.y * v.y;
#pragma unroll
    for (int o = 16; o; o >>= 1) ss += __shfl_xor_sync(0xFFFFFFFFu, ss, o);
    float inv = 1.0f / (sqrtf(ss) + 1e-6f);
    v.x *= inv; v.y *= inv;
    *(float2*)(p + lane * 2) = v;
}

// ---------------------------------------------------------------------------
// Dilated attention: one warp per (token, head). Output written pre-split
// (tf32 hi/lo interleaved) into G_AS for the second GEMM.
// ---------------------------------------------------------------------------
__global__ __launch_bounds__(256)
void attend_kernel()
{
    int gw   = (blockIdx.x * blockDim.x + threadIdx.x) >> 5;
    int lane = threadIdx.x & 31;
    if (gw >= M_TOTAL * N_HEADS) return;
    int r = gw >> 4;
    int h = gw & 15;
    int b = r / SEQ;
    int i = r % SEQ;

    const float* qp = G_QKV + (size_t)r * QKV_COLS + h * 64;
    const float* kb = G_QKV + (size_t)(b * SEQ) * QKV_COLS + D_MODEL + h * 64;
    const float* vb = G_QKV + (size_t)(b * SEQ) * QKV_COLS + 2 * D_MODEL + h * 64;

    float2 q = *(const float2*)(qp + lane * 2);

    float sc[17];
#pragma unroll
    for (int t = 0; t < 17; t++) {
        int j = i + 2 * (t - K_WIN);
        float s = -INFINITY;
        if (j >= 0 && j < SEQ) {
            float2 k = *(const float2*)(kb + (size_t)j * QKV_COLS + lane * 2);
            float d = q.x * k.x + q.y * k.y;
#pragma unroll
            for (int o = 16; o; o >>= 1) d += __shfl_xor_sync(0xFFFFFFFFu, d, o);
            s = d;
        }
        sc[t] = s;
    }

    float mx = -INFINITY;
#pragma unroll
    for (int t = 0; t < 17; t++) mx = fmaxf(mx, sc[t]);
    float den = 0.f;
#pragma unroll
    for (int t = 0; t < 17; t++) {
        float e = (sc[t] == -INFINITY) ? 0.f : __expf(sc[t] - mx);
        sc[t] = e;
        den += e;
    }
    float inv = 1.0f / den;   // den >= 1: diagonal always in window

    float2 acc = make_float2(0.f, 0.f);
#pragma unroll
    for (int t = 0; t < 17; t++) {
        int j = i + 2 * (t - K_WIN);
        if (j >= 0 && j < SEQ) {
            float2 v = *(const float2*)(vb + (size_t)j * QKV_COLS + lane * 2);
            float p = sc[t] * inv;
            acc.x = fmaf(p, v.x, acc.x);
            acc.y = fmaf(p, v.y, acc.y);
        }
    }

    // tf32 hi/lo split, interleaved: elem col e -> split cols 2e, 2e+1.
    uint4 w;
    tfpair(acc.x, w.x, w.y);
    tfpair(acc.y, w.z, w.w);
    *(uint4*)(G_AS + (size_t)r * K2 + 2 * (h * 64 + lane * 2)) = w;
}

// ---------------------------------------------------------------------------
// Launch (kernel launches + one attribute set; graph-capture safe)
// ---------------------------------------------------------------------------
extern "C" void kernel_launch(void* const* d_in, const int* in_sizes, int n_in,
                              void* d_out, int out_size)
{
    const float* x     = (const float*)d_in[0];
    const float* qkv_w = (const float*)d_in[1];
    const float* qkv_b = (const float*)d_in[2];
    const float* out_w = (const float*)d_in[3];
    const float* out_b = (const float*)d_in[4];
    float* out = (float*)d_out;

    cudaFuncSetAttribute(tf32_x_to_qkv,
                         cudaFuncAttributeMaxDynamicSharedMemorySize, GEMM_SMEM);
    cudaFuncSetAttribute(tf32_att_to_out,
                         cudaFuncAttributeMaxDynamicSharedMemorySize, GEMM_SMEM);

    // 0) Split prepasses (fp32 -> interleaved tf32 hi/lo)
    {
        int n4 = (M_TOTAL * D_MODEL) / 4;
        split_kernel<<<n4 / 256, 256>>>(x, 0, n4);
    }
    {
        int n4 = (QKV_COLS * D_MODEL) / 4;
        split_kernel<<<n4 / 256, 256>>>(qkv_w, 1, n4);
    }
    {
        int n4 = (D_MODEL * D_MODEL) / 4;
        split_kernel<<<n4 / 256, 256>>>(out_w, 2, n4);
    }

    // 1) QKV projection: G_XS @ G_WQ^T + qkv_b -> G_QKV fp32 (4096x3072)
    {
        dim3 grid(QKV_COLS / BN, M_TOTAL / BM);
        tf32_x_to_qkv<<<grid, 256, GEMM_SMEM>>>(qkv_b);
    }

    // 2) QK L2-normalization (in place on G_QKV)
    qknorm_kernel<<<(M_TOTAL * 32) / 8, 256>>>();

    // 3) Dilated windowed attention -> G_AS (tf32 hi/lo; aliases G_XS)
    attend_kernel<<<(M_TOTAL * N_HEADS) / 8, 256>>>();

    // 4) Output projection: G_AS @ G_WO^T + out_b -> out fp32 (4096x1024)
    {
        dim3 grid(D_MODEL / BN, M_TOTAL / BM);
        tf32_att_to_out<<<grid, 256, GEMM_SMEM>>>(out_b, out);
    }
}

// round 17
// speedup vs baseline: 1.9085x; 1.6710x over previous
#include <cuda_runtime.h>
#include <math.h>
#include <stdint.h>

#define D_MODEL 1024
#define N_HEADS 16
#define K_WIN   8
#define BATCH   2
#define SEQ     2048
#define M_TOTAL (BATCH * SEQ)          // 4096 tokens
#define QKV_COLS (3 * D_MODEL)         // 3072
#define KT      D_MODEL                // 1024 tf32 cols (single-term, rna-rounded)

// ---------------------------------------------------------------------------
// Scratch (__device__ globals, uint4-backed for 16B alignment).
// g_as (attention tf32 output) aliases g_xs: x is dead after GEMM1.
// ---------------------------------------------------------------------------
__device__ uint4 g_qkv4[((size_t)M_TOTAL * QKV_COLS * 4) / 16];   // fp32 qkv (50 MB)
__device__ uint4 g_xs4 [((size_t)M_TOTAL * KT * 4) / 16];         // tf32 x / attn (16 MB)
__device__ uint4 g_wq4 [((size_t)QKV_COLS * KT * 4) / 16];        // tf32 qkv_w (12 MB)
__device__ uint4 g_wo4 [((size_t)D_MODEL * KT * 4) / 16];         // tf32 out_w (4 MB)

#define G_QKV ((float*)g_qkv4)
#define G_XS  ((uint32_t*)g_xs4)
#define G_WQ  ((uint32_t*)g_wq4)
#define G_WO  ((uint32_t*)g_wo4)
#define G_AS  ((uint32_t*)g_xs4)

// ---------------------------------------------------------------------------
// tf32 helpers + cp.async
// ---------------------------------------------------------------------------
__device__ __forceinline__ uint32_t f2tf(float x) {
    uint32_t r;
    asm("cvt.rna.tf32.f32 %0, %1;" : "=r"(r) : "f"(x));
    return r;
}
__device__ __forceinline__ uint32_t smem_u32(const void* p) {
    uint32_t a;
    asm("{ .reg .u64 t; cvta.to.shared.u64 t, %1; cvt.u32.u64 %0, t; }"
        : "=r"(a) : "l"(p));
    return a;
}
__device__ __forceinline__ void cp_async16(uint32_t dst, const void* src) {
    asm volatile("cp.async.cg.shared.global [%0], [%1], 16;" :: "r"(dst), "l"(src));
}
#define CP_COMMIT() asm volatile("cp.async.commit_group;" ::: "memory")
#define CP_WAIT0()  asm volatile("cp.async.wait_group 0;" ::: "memory")

// Round to tf32 (rna) in place-format u32. mode: 0 -> G_XS, 1 -> G_WQ, 2 -> G_WO
__global__ __launch_bounds__(256)
void cvt_kernel(const float* __restrict__ src, int mode, int n4)
{
    int i = blockIdx.x * blockDim.x + threadIdx.x;
    if (i >= n4) return;
    uint32_t* dst = (mode == 0) ? G_XS : (mode == 1) ? G_WQ : G_WO;
    float4 v = __ldg((const float4*)src + i);
    uint4 w;
    w.x = f2tf(v.x);
    w.y = f2tf(v.y);
    w.z = f2tf(v.z);
    w.w = f2tf(v.w);
    *((uint4*)dst + i) = w;
}

// ---------------------------------------------------------------------------
// tf32 mma.sync GEMM, cp.async double-buffered, ONE __syncthreads per chunk
// (R16-proven schedule):
//   wait(chunk c) -> sync -> issue chunk c+1 into other buffer -> compute c
// CTA tile 128x128, BKT=32, 32 iterations (K=1024), 256 threads / 8 warps
// (64x32 warp tile, 64 fp32 accs). Dynamic smem: 2x2x128x36 u32 = 72 KB.
// ---------------------------------------------------------------------------
#define BM   128
#define BN   128
#define BKT  32
#define PADT 36              // 32 u32 + 4 pad; frag banks (4g+t) all distinct
#define GEMM_SMEM (2 * 2 * BM * PADT * 4)   // 73728 bytes

__device__ __forceinline__
void tf32_gemm_body(const uint32_t* __restrict__ A,
                    const uint32_t* __restrict__ B,
                    const float* __restrict__ bias,
                    float* __restrict__ C,
                    int N)
{
    extern __shared__ uint32_t smem_dyn[];
    uint32_t* const Abase = smem_dyn;
    uint32_t* const Bbase = smem_dyn + 2 * BM * PADT;

    const int tid    = threadIdx.x;
    const int wid    = tid >> 5;
    const int lane   = tid & 31;
    const int g      = lane >> 2;      // group 0..7
    const int t      = lane & 3;       // thread-in-group
    const int warp_m = wid & 1;        // 0..1 (64-row slabs)
    const int warp_n = wid >> 1;       // 0..3 (32-col slabs)

    const int bm = blockIdx.y * BM;
    const int bn = blockIdx.x * BN;
    const uint32_t* Arow = A + (size_t)bm * KT;
    const uint32_t* Brow = B + (size_t)bn * KT;

    // Loader: 1024 uint4 chunks per operand per K-chunk (128 rows x 8 u4-cols);
    // thread covers chunks tid, +256, +512, +768 for BOTH operands.
    const int r0 = tid >> 3,         c40 = (tid & 7) * 4;
    const int r1 = (tid + 256) >> 3, c41 = ((tid + 256) & 7) * 4;
    const int r2 = (tid + 512) >> 3, c42 = ((tid + 512) & 7) * 4;
    const int r3 = (tid + 768) >> 3, c43 = ((tid + 768) & 7) * 4;

    float acc[4][4][4];
#pragma unroll
    for (int i = 0; i < 4; i++)
#pragma unroll
        for (int j = 0; j < 4; j++)
#pragma unroll
            for (int e = 0; e < 4; e++) acc[i][j][e] = 0.f;

    const int NITER = KT / BKT;     // 32

#define ISSUE_CHUNK(k0, buf) do {                                             \
    uint32_t* Ab = Abase + (buf) * (BM * PADT);                               \
    uint32_t* Bb = Bbase + (buf) * (BN * PADT);                               \
    cp_async16(smem_u32(Ab + r0 * PADT + c40), Arow + (size_t)r0 * KT + (k0) + c40); \
    cp_async16(smem_u32(Ab + r1 * PADT + c41), Arow + (size_t)r1 * KT + (k0) + c41); \
    cp_async16(smem_u32(Ab + r2 * PADT + c42), Arow + (size_t)r2 * KT + (k0) + c42); \
    cp_async16(smem_u32(Ab + r3 * PADT + c43), Arow + (size_t)r3 * KT + (k0) + c43); \
    cp_async16(smem_u32(Bb + r0 * PADT + c40), Brow + (size_t)r0 * KT + (k0) + c40); \
    cp_async16(smem_u32(Bb + r1 * PADT + c41), Brow + (size_t)r1 * KT + (k0) + c41); \
    cp_async16(smem_u32(Bb + r2 * PADT + c42), Brow + (size_t)r2 * KT + (k0) + c42); \
    cp_async16(smem_u32(Bb + r3 * PADT + c43), Brow + (size_t)r3 * KT + (k0) + c43); \
    CP_COMMIT();                                                              \
} while (0)

    // Prologue: chunk 0 into buffer 0
    ISSUE_CHUNK(0, 0);

    for (int c = 0; c < NITER; c++) {
        const int buf = c & 1;
        CP_WAIT0();              // chunk c resident (only group in flight)
        __syncthreads();         // publish chunk c; all warps done with buf^1

        if (c + 1 < NITER)
            ISSUE_CHUNK((c + 1) * BKT, buf ^ 1);   // overlaps compute below

        const uint32_t* Ab = Abase + buf * (BM * PADT);
        const uint32_t* Bb = Bbase + buf * (BN * PADT);

#pragma unroll
        for (int s = 0; s < 4; s++) {
            const int kb = s * 8;
            const uint32_t* Bw = Bb + (warp_n * 32 + g) * PADT + kb + t;
            const uint32_t b00 = Bw[0 * 8 * PADT];
            const uint32_t b01 = Bw[0 * 8 * PADT + 4];
            const uint32_t b10 = Bw[1 * 8 * PADT];
            const uint32_t b11 = Bw[1 * 8 * PADT + 4];
            const uint32_t b20 = Bw[2 * 8 * PADT];
            const uint32_t b21 = Bw[2 * 8 * PADT + 4];
            const uint32_t b30 = Bw[3 * 8 * PADT];
            const uint32_t b31 = Bw[3 * 8 * PADT + 4];
#pragma unroll
            for (int mf = 0; mf < 4; mf++) {
                const uint32_t* Aw = Ab + (warp_m * 64 + mf * 16 + g) * PADT + kb + t;
                const uint32_t a0 = Aw[0];
                const uint32_t a1 = Aw[8 * PADT];
                const uint32_t a2 = Aw[4];
                const uint32_t a3 = Aw[8 * PADT + 4];
#define TF32_MMA(nf, bb0, bb1)                                          \
                asm volatile(                                           \
                    "mma.sync.aligned.m16n8k8.row.col.f32.tf32.tf32.f32 " \
                    "{%0,%1,%2,%3}, {%4,%5,%6,%7}, {%8,%9}, {%0,%1,%2,%3};" \
                    : "+f"(acc[mf][nf][0]), "+f"(acc[mf][nf][1]),       \
                      "+f"(acc[mf][nf][2]), "+f"(acc[mf][nf][3])        \
                    : "r"(a0), "r"(a1), "r"(a2), "r"(a3), "r"(bb0), "r"(bb1))
                TF32_MMA(0, b00, b01);
                TF32_MMA(1, b10, b11);
                TF32_MMA(2, b20, b21);
                TF32_MMA(3, b30, b31);
#undef TF32_MMA
            }
        }
        // no trailing sync: next iteration's barrier provides the ordering
    }
#undef ISSUE_CHUNK

    // Epilogue: acc e0,e1 -> (row g, cols 2t,2t+1); e2,e3 -> (row g+8).
#pragma unroll
    for (int mf = 0; mf < 4; mf++) {
        const int gr = bm + warp_m * 64 + mf * 16 + g;
#pragma unroll
        for (int nf = 0; nf < 4; nf++) {
            const int gc = bn + warp_n * 32 + nf * 8 + t * 2;
            const float b0 = __ldg(bias + gc);
            const float b1 = __ldg(bias + gc + 1);
            float2 v0 = make_float2(acc[mf][nf][0] + b0, acc[mf][nf][1] + b1);
            float2 v1 = make_float2(acc[mf][nf][2] + b0, acc[mf][nf][3] + b1);
            *(float2*)(C + (size_t)gr * N + gc)       = v0;
            *(float2*)(C + (size_t)(gr + 8) * N + gc) = v1;
        }
    }
}

__global__ __launch_bounds__(256)
void tf32_x_to_qkv(const float* __restrict__ qkv_b)
{
    tf32_gemm_body(G_XS, G_WQ, qkv_b, G_QKV, QKV_COLS);
}

__global__ __launch_bounds__(256)
void tf32_att_to_out(const float* __restrict__ out_b, float* __restrict__ out)
{
    tf32_gemm_body(G_AS, G_WO, out_b, out, D_MODEL);
}

// ---------------------------------------------------------------------------
// QK-norm: L2-normalize each 64-element head vector of q and k (in place).
// ---------------------------------------------------------------------------
__global__ __launch_bounds__(256)
void qknorm_kernel()
{
    int gw   = (blockIdx.x * blockDim.x + threadIdx.x) >> 5;
    int lane = threadIdx.x & 31;
    if (gw >= M_TOTAL * 32) return;
    int row = gw >> 5;
    int seg = gw & 31;
    size_t off = (size_t)row * QKV_COLS +
                 (seg < 16 ? seg * 64 : D_MODEL + (seg - 16) * 64);
    float* p = G_QKV + off;
    float2 v = *(float2*)(p + lane * 2);
    float ss = v.x * v.x + v.y * v.y;
#pragma unroll
    for (int o = 16; o; o >>= 1) ss += __shfl_xor_sync(0xFFFFFFFFu, ss, o);
    float inv = 1.0f / (sqrtf(ss) + 1e-6f);
    v.x *= inv; v.y *= inv;
    *(float2*)(p + lane * 2) = v;
}

// ---------------------------------------------------------------------------
// Dilated attention: one warp per (token, head). Output written tf32-rounded
// (rna) into G_AS for the second GEMM.
// ---------------------------------------------------------------------------
__global__ __launch_bounds__(256)
void attend_kernel()
{
    int gw   = (blockIdx.x * blockDim.x + threadIdx.x) >> 5;
    int lane = threadIdx.x & 31;
    if (gw >= M_TOTAL * N_HEADS) return;
    int r = gw >> 4;
    int h = gw & 15;
    int b = r / SEQ;
    int i = r % SEQ;

    const float* qp = G_QKV + (size_t)r * QKV_COLS + h * 64;
    const float* kb = G_QKV + (size_t)(b * SEQ) * QKV_COLS + D_MODEL + h * 64;
    const float* vb = G_QKV + (size_t)(b * SEQ) * QKV_COLS + 2 * D_MODEL + h * 64;

    float2 q = *(const float2*)(qp + lane * 2);

    float sc[17];
#pragma unroll
    for (int t = 0; t < 17; t++) {
        int j = i + 2 * (t - K_WIN);
        float s = -INFINITY;
        if (j >= 0 && j < SEQ) {
            float2 k = *(const float2*)(kb + (size_t)j * QKV_COLS + lane * 2);
            float d = q.x * k.x + q.y * k.y;
#pragma unroll
            for (int o = 16; o; o >>= 1) d += __shfl_xor_sync(0xFFFFFFFFu, d, o);
            s = d;
        }
        sc[t] = s;
    }

    float mx = -INFINITY;
#pragma unroll
    for (int t = 0; t < 17; t++) mx = fmaxf(mx, sc[t]);
    float den = 0.f;
#pragma unroll
    for (int t = 0; t < 17; t++) {
        float e = (sc[t] == -INFINITY) ? 0.f : __expf(sc[t] - mx);
        sc[t] = e;
        den += e;
    }
    float inv = 1.0f / den;   // den >= 1: diagonal always in window

    float2 acc = make_float2(0.f, 0.f);
#pragma unroll
    for (int t = 0; t < 17; t++) {
        int j = i + 2 * (t - K_WIN);
        if (j >= 0 && j < SEQ) {
            float2 v = *(const float2*)(vb + (size_t)j * QKV_COLS + lane * 2);
            float p = sc[t] * inv;
            acc.x = fmaf(p, v.x, acc.x);
            acc.y = fmaf(p, v.y, acc.y);
        }
    }

    // tf32-rounded store (col = h*64 + lane*2, uint2-aligned)
    uint2 w;
    w.x = f2tf(acc.x);
    w.y = f2tf(acc.y);
    *(uint2*)(G_AS + (size_t)r * KT + h * 64 + lane * 2) = w;
}

// ---------------------------------------------------------------------------
// Launch (kernel launches + attribute sets; graph-capture safe)
// ---------------------------------------------------------------------------
extern "C" void kernel_launch(void* const* d_in, const int* in_sizes, int n_in,
                              void* d_out, int out_size)
{
    const float* x     = (const float*)d_in[0];
    const float* qkv_w = (const float*)d_in[1];
    const float* qkv_b = (const float*)d_in[2];
    const float* out_w = (const float*)d_in[3];
    const float* out_b = (const float*)d_in[4];
    float* out = (float*)d_out;

    cudaFuncSetAttribute(tf32_x_to_qkv,
                         cudaFuncAttributeMaxDynamicSharedMemorySize, GEMM_SMEM);
    cudaFuncSetAttribute(tf32_att_to_out,
                         cudaFuncAttributeMaxDynamicSharedMemorySize, GEMM_SMEM);

    // 0) Rounding prepasses (fp32 -> tf32-rna u32, same element count)
    {
        int n4 = (M_TOTAL * D_MODEL) / 4;
        cvt_kernel<<<n4 / 256, 256>>>(x, 0, n4);
    }
    {
        int n4 = (QKV_COLS * D_MODEL) / 4;
        cvt_kernel<<<n4 / 256, 256>>>(qkv_w, 1, n4);
    }
    {
        int n4 = (D_MODEL * D_MODEL) / 4;
        cvt_kernel<<<n4 / 256, 256>>>(out_w, 2, n4);
    }

    // 1) QKV projection: G_XS @ G_WQ^T + qkv_b -> G_QKV fp32 (4096x3072)
    {
        dim3 grid(QKV_COLS / BN, M_TOTAL / BM);
        tf32_x_to_qkv<<<grid, 256, GEMM_SMEM>>>(qkv_b);
    }

    // 2) QK L2-normalization (in place on G_QKV)
    qknorm_kernel<<<(M_TOTAL * 32) / 8, 256>>>();

    // 3) Dilated windowed attention -> G_AS (tf32; aliases G_XS)
    attend_kernel<<<(M_TOTAL * N_HEADS) / 8, 256>>>();

    // 4) Output projection: G_AS @ G_WO^T + out_b -> out fp32 (4096x1024)
    {
        dim3 grid(D_MODEL / BN, M_TOTAL / BM);
        tf32_att_to_out<<<grid, 256, GEMM_SMEM>>>(out_b, out);
    }
}